// round 5
// baseline (speedup 1.0000x reference)
#include <cuda_runtime.h>
#include <cuda_bf16.h>

#define DIM    2048
#define BATCH  32
#define KTOP   256
#define LOG2E  1.44269504f
#define SORT_T 512

// Bsum[b][i] * log2e  (32*2048 floats)
__device__ float g_bsum[BATCH * DIM];

__device__ __forceinline__ float ex2f(float x) {
    float r; asm("ex2.approx.ftz.f32 %0, %1;" : "=f"(r) : "f"(x)); return r;
}
__device__ __forceinline__ float rcpf(float x) {
    float r; asm("rcp.approx.f32 %0, %1;" : "=f"(r) : "f"(x)); return r;
}

// ---------------------------------------------------------------------------
// Kernel 1: Bsum via bitonic sort + prefix sum (O(n log n) per row).
// One block per batch row. Sort (sortable-key, idx) u64 pairs in smem,
// block-scan the sorted values, then  B_r = v_r*(2r-n) + T - 2*P_r,
// scattered back to original index (pre-scaled by log2e).
// ---------------------------------------------------------------------------
__global__ __launch_bounds__(SORT_T) void bsum_sort_kernel(const float* __restrict__ scores) {
    __shared__ unsigned long long kv[DIM];      // 16 KB
    __shared__ float wsum[17];                  // 16 warp sums + total
    const int b = blockIdx.x;
    const int t = threadIdx.x;
    const int lane = t & 31, w = t >> 5;
    const float* row = scores + b * DIM;

    // load + build monotonic keys: u ^= (neg ? 0xFFFFFFFF : 0x80000000)
    #pragma unroll
    for (int c = 0; c < DIM / SORT_T; c++) {
        int i = t + c * SORT_T;
        unsigned int u = __float_as_uint(row[i]);
        u ^= (unsigned int)(((int)u >> 31)) | 0x80000000u;
        kv[i] = ((unsigned long long)u << 32) | (unsigned int)i;
    }
    __syncthreads();

    // bitonic sort ascending (66 substages)
    for (int k = 2; k <= DIM; k <<= 1) {
        for (int j = k >> 1; j > 0; j >>= 1) {
            #pragma unroll
            for (int c = 0; c < DIM / SORT_T; c++) {
                int i = t + c * SORT_T;
                int ixj = i ^ j;
                if (ixj > i) {
                    unsigned long long a = kv[i], bb = kv[ixj];
                    bool up = ((i & k) == 0);
                    if ((a > bb) == up) { kv[i] = bb; kv[ixj] = a; }
                }
            }
            __syncthreads();
        }
    }

    // decode this thread's 4 contiguous sorted values + indices
    const int r0 = t * 4;
    float v[4]; int idx[4];
    #pragma unroll
    for (int m = 0; m < 4; m++) {
        unsigned long long e = kv[r0 + m];
        unsigned int u = (unsigned int)(e >> 32);
        u ^= (~(unsigned int)(((int)u >> 31))) | 0x80000000u;
        v[m]   = __uint_as_float(u);
        idx[m] = (int)(unsigned int)(e & 0xFFFFFFFFu);
    }

    // block exclusive scan of sorted values
    float lp1 = v[0];
    float lp2 = lp1 + v[1];
    float lp3 = lp2 + v[2];
    float lsum = lp3 + v[3];

    float x = lsum;                                  // warp inclusive scan
    #pragma unroll
    for (int o = 1; o < 32; o <<= 1) {
        float y = __shfl_up_sync(0xffffffffu, x, o);
        if (lane >= o) x += y;
    }
    if (lane == 31) wsum[w] = x;
    __syncthreads();
    if (t == 0) {
        float acc = 0.f;
        #pragma unroll
        for (int i = 0; i < 16; i++) { float tmp = wsum[i]; wsum[i] = acc; acc += tmp; }
        wsum[16] = acc;
    }
    __syncthreads();
    const float base = wsum[w] + (x - lsum);         // exclusive prefix at r0
    const float T = wsum[16];

    // B_r = v*(2r - n) + T - 2*P_r  (P exclusive), scatter by original idx
    float P[4] = {base, base + lp1, base + lp2, base + lp3};
    #pragma unroll
    for (int m = 0; m < 4; m++) {
        int r = r0 + m;
        float B = fmaf(v[m], (float)(2 * r - DIM), T - 2.f * P[m]);
        g_bsum[(b << 11) + idx[m]] = B * LOG2E;
    }
}

// ---------------------------------------------------------------------------
// Kernel 2: fused logit + softmax + write, KPB=8 per block, lean reductions.
// Grid (32 kg, 32 b) x 256 threads, 8 elems/thread. Block fold is
// warp-butterfly -> lane0 STS -> bar -> LDS red[lane&7] + 3-step shfl-bfly.
// s and B are pre-scaled by log2e so exp is a bare EX2.
// ---------------------------------------------------------------------------
__global__ __launch_bounds__(256) void softmax_kernel(const float* __restrict__ scores,
                                                      float* __restrict__ out) {
    __shared__ float2 sb[DIM];                       // (s*log2e, B*log2e), 16 KB
    __shared__ float redM[8];
    __shared__ float redS[8];
    const int kg = blockIdx.x;
    const int b  = blockIdx.y;
    const int t  = threadIdx.x;
    const int lane = t & 31, w = t >> 5;

    {   // stage
        const float4* sc4 = (const float4*)(scores + (b << 11));
        const float4* bs4 = (const float4*)(g_bsum + (b << 11));
        float4* d4 = (float4*)sb;
        #pragma unroll
        for (int c = 0; c < 2; c++) {
            int j = t + c * 256;
            float4 s = sc4[j], u = bs4[j];
            d4[j * 2 + 0] = make_float4(s.x * LOG2E, u.x, s.y * LOG2E, u.y);
            d4[j * 2 + 1] = make_float4(s.z * LOG2E, u.z, s.w * LOG2E, u.w);
        }
    }
    __syncthreads();

    // per-thread resident data: elems 4t..4t+3 and 1024+4t..1024+4t+3
    const float4* sb4 = (const float4*)sb;
    const float4 u0 = sb4[2 * t];
    const float4 u1 = sb4[2 * t + 1];
    const float4 u2 = sb4[512 + 2 * t];
    const float4 u3 = sb4[513 + 2 * t];

    #pragma unroll
    for (int kk = 0; kk < 8; kk++) {
        const int k = (kg << 3) + kk;
        const float scal = (float)(DIM - 1 - 2 * k);

        float l[8];
        l[0] = fmaf(u0.x, scal, -u0.y);
        l[1] = fmaf(u0.z, scal, -u0.w);
        l[2] = fmaf(u1.x, scal, -u1.y);
        l[3] = fmaf(u1.z, scal, -u1.w);
        l[4] = fmaf(u2.x, scal, -u2.y);
        l[5] = fmaf(u2.z, scal, -u2.w);
        l[6] = fmaf(u3.x, scal, -u3.y);
        l[7] = fmaf(u3.z, scal, -u3.w);

        // local max tree + warp butterfly
        float m = fmaxf(fmaxf(fmaxf(l[0], l[1]), fmaxf(l[2], l[3])),
                        fmaxf(fmaxf(l[4], l[5]), fmaxf(l[6], l[7])));
        #pragma unroll
        for (int o = 16; o; o >>= 1) m = fmaxf(m, __shfl_xor_sync(0xffffffffu, m, o));
        if (lane == 0) redM[w] = m;
        __syncthreads();
        // lean cross-warp fold: 1 LDS + 3-step bfly over 8-lane groups
        float M = redM[lane & 7];
        #pragma unroll
        for (int o = 4; o; o >>= 1) M = fmaxf(M, __shfl_xor_sync(0xffffffffu, M, o));

        // exp2 + sum
        float s0 = 0.f, s1 = 0.f;
        #pragma unroll
        for (int i = 0; i < 8; i += 2) {
            l[i]     = ex2f(l[i] - M);
            l[i + 1] = ex2f(l[i + 1] - M);
            s0 += l[i];
            s1 += l[i + 1];
        }
        float s = s0 + s1;
        #pragma unroll
        for (int o = 16; o; o >>= 1) s += __shfl_xor_sync(0xffffffffu, s, o);
        if (lane == 0) redS[w] = s;
        __syncthreads();
        float S = redS[lane & 7];
        #pragma unroll
        for (int o = 4; o; o >>= 1) S += __shfl_xor_sync(0xffffffffu, S, o);

        const float inv = rcpf(S);

        float4* out4 = (float4*)(out + ((size_t)((b << 8) + k) << 11));
        out4[t]       = make_float4(l[0] * inv, l[1] * inv, l[2] * inv, l[3] * inv);
        out4[256 + t] = make_float4(l[4] * inv, l[5] * inv, l[6] * inv, l[7] * inv);
    }
}

extern "C" void kernel_launch(void* const* d_in, const int* in_sizes, int n_in,
                              void* d_out, int out_size) {
    const float* scores = (const float*)d_in[0];
    float* out = (float*)d_out;

    bsum_sort_kernel<<<BATCH, SORT_T>>>(scores);
    softmax_kernel<<<dim3(KTOP / 8, BATCH), 256>>>(scores, out);
}

// round 6
// speedup vs baseline: 1.0520x; 1.0520x over previous
#include <cuda_runtime.h>
#include <cuda_bf16.h>

#define DIM    2048
#define BATCH  32
#define KTOP   256
#define LOG2E  1.44269504f

// Bsum[b][i] * log2e
__device__ float g_bsum[BATCH * DIM];
// C[b][k] = M2[b,k] + log2(S2[b,k])  (base-2 softmax constant)
__device__ float g_C[BATCH * KTOP];

__device__ __forceinline__ float ex2f(float x) {
    float r; asm("ex2.approx.ftz.f32 %0, %1;" : "=f"(r) : "f"(x)); return r;
}
__device__ __forceinline__ float lg2f(float x) {
    float r; asm("lg2.approx.f32 %0, %1;" : "=f"(r) : "f"(x)); return r;
}

// bitonic compare-exchange via shfl (element index bit (e&j) == (t&j) here)
__device__ __forceinline__ unsigned long long cmpex_shfl(unsigned long long v,
                                                         int t, int j, bool dir) {
    unsigned long long o = __shfl_xor_sync(0xffffffffu, v, j);
    bool takeMin = (((t & j) == 0) == dir);
    bool take = takeMin ? (o < v) : (o > v);
    return take ? o : v;
}

// ---------------------------------------------------------------------------
// Kernel 1: Bsum via register bitonic sort + prefix sum.
// 32 blocks x 1024 threads; thread t holds elements t and t+1024 in regs.
// j<=16 substages: shfl (no barrier). j=1024: intra-thread. j=32..512: smem
// (20 substages instead of 66). Then block scan + closed form
// B_r = v_r*(2r-n) + T - 2*P_r scattered by original index (x log2e).
// ---------------------------------------------------------------------------
__global__ __launch_bounds__(1024) void bsum_sort_kernel(const float* __restrict__ scores) {
    __shared__ unsigned long long ex[DIM];   // 16 KB exchange buffer
    __shared__ float wsc[65];                // 2x32 warp sums + total
    const int b = blockIdx.x;
    const int t = threadIdx.x;
    const int lane = t & 31, w = t >> 5;
    const float* row = scores + (b << 11);

    // load + monotonic key transform, payload = original index
    unsigned long long v0, v1;
    {
        unsigned int u0 = __float_as_uint(row[t]);
        u0 ^= ((unsigned int)((int)u0 >> 31)) | 0x80000000u;
        v0 = ((unsigned long long)u0 << 32) | (unsigned int)t;
        unsigned int u1 = __float_as_uint(row[t + 1024]);
        u1 ^= ((unsigned int)((int)u1 >> 31)) | 0x80000000u;
        v1 = ((unsigned long long)u1 << 32) | (unsigned int)(t + 1024);
    }

    // stages k=2..32: fully intra-warp (shfl), dir = ((e&k)==0) = ((t&k)==0)
    #pragma unroll
    for (int k = 2; k <= 32; k <<= 1) {
        const bool d = ((t & k) == 0);
        #pragma unroll
        for (int j = k >> 1; j > 0; j >>= 1) {
            v0 = cmpex_shfl(v0, t, j, d);
            v1 = cmpex_shfl(v1, t, j, d);
        }
    }

    // stages k=64..2048
    #pragma unroll
    for (int k = 64; k <= 2048; k <<= 1) {
        const bool d0 = ((t & k) == 0);           // element e = t
        const bool d1 = (((t | 1024) & k) == 0);  // element e = t+1024
        #pragma unroll
        for (int j = k >> 1; j > 0; j >>= 1) {
            if (j == 1024) {                       // k=2048 only: intra-thread, ascending
                unsigned long long lo = v0 < v1 ? v0 : v1;
                unsigned long long hi = v0 < v1 ? v1 : v0;
                v0 = lo; v1 = hi;
            } else if (j >= 32) {                  // cross-warp: smem exchange
                __syncthreads();
                ex[t] = v0; ex[t + 1024] = v1;
                __syncthreads();
                unsigned long long o0 = ex[t ^ j];
                unsigned long long o1 = ex[(t ^ j) + 1024];
                bool tj = ((t & j) == 0);
                bool tm0 = (tj == d0);
                bool tm1 = (tj == d1);
                v0 = (tm0 ? (o0 < v0) : (o0 > v0)) ? o0 : v0;
                v1 = (tm1 ? (o1 < v1) : (o1 > v1)) ? o1 : v1;
            } else {                               // intra-warp
                v0 = cmpex_shfl(v0, t, j, d0);
                v1 = cmpex_shfl(v1, t, j, d1);
            }
        }
    }

    // decode sorted values (v0 at position t, v1 at position t+1024)
    float f0, f1; unsigned int i0, i1;
    {
        unsigned int u = (unsigned int)(v0 >> 32);
        u ^= (~(unsigned int)((int)u >> 31)) | 0x80000000u;
        f0 = __uint_as_float(u);
        i0 = (unsigned int)(v0 & 0xFFFFFFFFu);
        u = (unsigned int)(v1 >> 32);
        u ^= (~(unsigned int)((int)u >> 31)) | 0x80000000u;
        f1 = __uint_as_float(u);
        i1 = (unsigned int)(v1 & 0xFFFFFFFFu);
    }

    // block inclusive scans: positions 0..1023 (f0), 1024..2047 (f1)
    float x0 = f0, x1 = f1;
    #pragma unroll
    for (int o = 1; o < 32; o <<= 1) {
        float y0 = __shfl_up_sync(0xffffffffu, x0, o);
        float y1 = __shfl_up_sync(0xffffffffu, x1, o);
        if (lane >= o) { x0 += y0; x1 += y1; }
    }
    if (lane == 31) { wsc[w] = x0; wsc[32 + w] = x1; }
    __syncthreads();
    if (w == 0) {
        float a = wsc[lane], sa = a;
        float c = wsc[32 + lane], sc = c;
        #pragma unroll
        for (int o = 1; o < 32; o <<= 1) {
            float ya = __shfl_up_sync(0xffffffffu, a, o);
            float yc = __shfl_up_sync(0xffffffffu, c, o);
            if (lane >= o) { a += ya; c += yc; }
        }
        float T0 = __shfl_sync(0xffffffffu, a, 31);
        wsc[lane] = a - sa;              // exclusive base, first-half warps
        wsc[32 + lane] = T0 + (c - sc);  // exclusive base, second-half warps
        if (lane == 31) wsc[64] = T0 + c;
    }
    __syncthreads();

    const float P0 = wsc[w] + (x0 - f0);        // exclusive prefix at pos t
    const float P1 = wsc[32 + w] + (x1 - f1);   // at pos t+1024
    const float T = wsc[64];

    float B0 = fmaf(f0, (float)(2 * t - DIM), T - 2.f * P0);
    float B1 = fmaf(f1, (float)(2 * (t + 1024) - DIM), T - 2.f * P1);
    g_bsum[(b << 11) + i0] = B0 * LOG2E;
    g_bsum[(b << 11) + i1] = B1 * LOG2E;
}

// ---------------------------------------------------------------------------
// Kernel 2: stats — C[b,k] = M + log2(S) in the base-2 logit domain.
// Grid (32 kg, 32 b) x 256 threads. Block stages (s*log2e, B') once in smem;
// each of the 8 warps owns one k and does a private streaming max pass and
// exp2-sum pass with warp-shuffle reductions only (reductions once per 2048
// elements, not once per 256).
// ---------------------------------------------------------------------------
__global__ __launch_bounds__(256) void stats_kernel(const float* __restrict__ scores) {
    __shared__ float2 sb[DIM];                  // 16 KB
    const int kg = blockIdx.x;
    const int b  = blockIdx.y;
    const int t  = threadIdx.x;
    const int lane = t & 31, w = t >> 5;

    {
        const float4* sc4 = (const float4*)(scores + (b << 11));
        const float4* bs4 = (const float4*)(g_bsum + (b << 11));
        float4* d4 = (float4*)sb;
        #pragma unroll
        for (int c = 0; c < 2; c++) {
            int j = t + c * 256;
            float4 s = sc4[j], u = bs4[j];
            d4[j * 2 + 0] = make_float4(s.x * LOG2E, u.x, s.y * LOG2E, u.y);
            d4[j * 2 + 1] = make_float4(s.z * LOG2E, u.z, s.w * LOG2E, u.w);
        }
    }
    __syncthreads();

    const int k = (kg << 3) + w;
    const float scal = (float)(DIM - 1 - 2 * k);
    const float4* p = (const float4*)sb;        // p[i] = (s'_{2i},B'_{2i},s'_{2i+1},B'_{2i+1})

    // pass 1: max
    float m0 = -3.4e38f, m1 = -3.4e38f;
    #pragma unroll 8
    for (int i = lane; i < DIM / 2; i += 32) {
        float4 u = p[i];
        m0 = fmaxf(m0, fmaf(u.x, scal, -u.y));
        m1 = fmaxf(m1, fmaf(u.z, scal, -u.w));
    }
    float M = fmaxf(m0, m1);
    #pragma unroll
    for (int o = 16; o; o >>= 1) M = fmaxf(M, __shfl_xor_sync(0xffffffffu, M, o));

    // pass 2: sum of exp2
    float s0 = 0.f, s1 = 0.f;
    #pragma unroll 8
    for (int i = lane; i < DIM / 2; i += 32) {
        float4 u = p[i];
        s0 += ex2f(fmaf(u.x, scal, -u.y) - M);
        s1 += ex2f(fmaf(u.z, scal, -u.w) - M);
    }
    float S = s0 + s1;
    #pragma unroll
    for (int o = 16; o; o >>= 1) S += __shfl_xor_sync(0xffffffffu, S, o);

    if (lane == 0) g_C[(b << 8) + k] = M + lg2f(S);
}

// ---------------------------------------------------------------------------
// Kernel 3: writer — out = 2^(s'*scal - B' - C). NO smem, NO barriers, NO
// shuffles. Grid (32 kg, 32 b) x 256 threads; each thread keeps its 8
// (s',B') in registers across 8 k's. Bound by STG.128 issue + MUFU, both
// streaming.
// ---------------------------------------------------------------------------
__global__ __launch_bounds__(256) void writer_kernel(const float* __restrict__ scores,
                                                     float* __restrict__ out) {
    const int kg = blockIdx.x;
    const int b  = blockIdx.y;
    const int t  = threadIdx.x;

    const float4* sc4 = (const float4*)(scores + (b << 11));
    const float4* bs4 = (const float4*)(g_bsum + (b << 11));
    float4 a0 = sc4[t], a1 = sc4[t + 256];
    const float4 c0 = bs4[t], c1 = bs4[t + 256];
    a0.x *= LOG2E; a0.y *= LOG2E; a0.z *= LOG2E; a0.w *= LOG2E;
    a1.x *= LOG2E; a1.y *= LOG2E; a1.z *= LOG2E; a1.w *= LOG2E;

    #pragma unroll
    for (int kk = 0; kk < 8; kk++) {
        const int k = (kg << 3) + kk;
        const float scal = (float)(DIM - 1 - 2 * k);
        const float C = __ldg(&g_C[(b << 8) + k]);

        float4 o0, o1;
        o0.x = ex2f(fmaf(a0.x, scal, -c0.x) - C);
        o0.y = ex2f(fmaf(a0.y, scal, -c0.y) - C);
        o0.z = ex2f(fmaf(a0.z, scal, -c0.z) - C);
        o0.w = ex2f(fmaf(a0.w, scal, -c0.w) - C);
        o1.x = ex2f(fmaf(a1.x, scal, -c1.x) - C);
        o1.y = ex2f(fmaf(a1.y, scal, -c1.y) - C);
        o1.z = ex2f(fmaf(a1.z, scal, -c1.z) - C);
        o1.w = ex2f(fmaf(a1.w, scal, -c1.w) - C);

        float4* out4 = (float4*)(out + ((size_t)((b << 8) + k) << 11));
        out4[t]       = o0;
        out4[t + 256] = o1;
    }
}

extern "C" void kernel_launch(void* const* d_in, const int* in_sizes, int n_in,
                              void* d_out, int out_size) {
    const float* scores = (const float*)d_in[0];
    float* out = (float*)d_out;

    bsum_sort_kernel<<<BATCH, 1024>>>(scores);
    stats_kernel<<<dim3(KTOP / 8, BATCH), 256>>>(scores);
    writer_kernel<<<dim3(KTOP / 8, BATCH), 256>>>(scores, out);
}

// round 8
// speedup vs baseline: 1.5678x; 1.4903x over previous
#include <cuda_runtime.h>
#include <cuda_bf16.h>

#define DIM    2048
#define BATCH  32
#define KTOP   256
#define LOG2E  1.44269504f

// sorted chunk keys [b][chunk][256]: (monotonic u32 key << 32) | global index
__device__ __align__(16) unsigned long long g_key[BATCH * DIM];
// inclusive prefix sums of values in chunk-sorted order, same layout
__device__ __align__(16) float g_pref[BATCH * DIM];
// Bsum * log2e, original index order
__device__ __align__(16) float g_bsum[BATCH * DIM];
// top-256 by global rank: slot r-1792 holds (s*log2e, B*log2e) of rank-r element
__device__ __align__(16) float g_topv[BATCH * KTOP];
__device__ __align__(16) float g_topB[BATCH * KTOP];

__device__ __forceinline__ float ex2f(float x) {
    float r; asm("ex2.approx.ftz.f32 %0, %1;" : "=f"(r) : "f"(x)); return r;
}
__device__ __forceinline__ float rcpf(float x) {
    float r; asm("rcp.approx.f32 %0, %1;" : "=f"(r) : "f"(x)); return r;
}
__device__ __forceinline__ unsigned long long cmpex_shfl(unsigned long long v,
                                                         int t, int j, bool d) {
    unsigned long long o = __shfl_xor_sync(0xffffffffu, v, j);
    bool takeMin = (((t & j) == 0) == d);
    return (takeMin ? (o < v) : (o > v)) ? o : v;
}

// ---------------------------------------------------------------------------
// Kernel A: sort each 256-element chunk (strict total order via packed
// (key,idx) u64) and compute inclusive value-prefix sums in sorted order.
// Grid (8 chunks, 32 b) x 256 threads, 1 element/thread in registers.
// ---------------------------------------------------------------------------
__global__ __launch_bounds__(256) void chunk_sort_kernel(const float* __restrict__ scores) {
    __shared__ unsigned long long buf[256];
    __shared__ float wtot[8];
    const int chunk = blockIdx.x, b = blockIdx.y, t = threadIdx.x;
    const int lane = t & 31, w = t >> 5;
    const int gi = (chunk << 8) + t;

    unsigned long long K;
    {
        unsigned int u = __float_as_uint(scores[(b << 11) + gi]);
        u ^= ((unsigned int)((int)u >> 31)) | 0x80000000u;
        K = ((unsigned long long)u << 32) | (unsigned int)gi;
    }

    // stages k=2..32: intra-warp shfl
    #pragma unroll
    for (int k = 2; k <= 32; k <<= 1) {
        const bool d = ((t & k) == 0);
        #pragma unroll
        for (int j = k >> 1; j > 0; j >>= 1) K = cmpex_shfl(K, t, j, d);
    }
    // stages k=64..256: j>=32 via smem, rest shfl
    #pragma unroll
    for (int k = 64; k <= 256; k <<= 1) {
        const bool d = ((t & k) == 0);
        #pragma unroll
        for (int j = k >> 1; j > 0; j >>= 1) {
            if (j >= 32) {
                __syncthreads();
                buf[t] = K;
                __syncthreads();
                unsigned long long o = buf[t ^ j];
                bool takeMin = (((t & j) == 0) == d);
                K = (takeMin ? (o < K) : (o > K)) ? o : K;
            } else {
                K = cmpex_shfl(K, t, j, d);
            }
        }
    }

    // decode value at sorted position t
    float v;
    {
        unsigned int u = (unsigned int)(K >> 32);
        u ^= (~((unsigned int)((int)u >> 31))) | 0x80000000u;
        v = __uint_as_float(u);
    }

    // inclusive block scan of v
    float x = v;
    #pragma unroll
    for (int o = 1; o < 32; o <<= 1) {
        float y = __shfl_up_sync(0xffffffffu, x, o);
        if (lane >= o) x += y;
    }
    if (lane == 31) wtot[w] = x;
    __syncthreads();
    float off = 0.f;
    #pragma unroll
    for (int ww = 0; ww < 7; ww++) if (ww < w) off += wtot[ww];

    const int o = (b << 11) + gi;   // [b][chunk][sorted pos t]
    g_key[o]  = K;
    g_pref[o] = off + x;
}

// ---------------------------------------------------------------------------
// Kernel B: Bsum via 8 interleaved branchless binary searches over the sorted
// chunks (staged in smem), plus top-256 scatter by global rank.
// Grid (8 ichunks, 32 b) x 256 threads; r_i and P_i decompose over chunks.
// B_i = s_i*(2r-n) + T - 2P ; rank 2047-k element is the softmax argmax.
// ---------------------------------------------------------------------------
__global__ __launch_bounds__(256) void bsum_search_kernel(const float* __restrict__ scores) {
    __shared__ __align__(16) unsigned long long skey[DIM];  // 16 KB
    __shared__ __align__(16) float spref[DIM];              // 8 KB
    const int ic = blockIdx.x, b = blockIdx.y, t = threadIdx.x;

    {   // stage the whole row's sorted chunks
        const ulonglong2* gk2 = (const ulonglong2*)(g_key + (b << 11));
        ulonglong2* sk2 = (ulonglong2*)skey;
        #pragma unroll
        for (int c = 0; c < 4; c++) sk2[t + c * 256] = gk2[t + c * 256];
        const float4* gp4 = (const float4*)(g_pref + (b << 11));
        float4* sp4 = (float4*)spref;
        #pragma unroll
        for (int c = 0; c < 2; c++) sp4[t + c * 256] = gp4[t + c * 256];
    }
    __syncthreads();

    const int i = (ic << 8) + t;
    const float s = scores[(b << 11) + i];
    unsigned long long K;
    {
        unsigned int u = __float_as_uint(s);
        u ^= ((unsigned int)((int)u >> 31)) | 0x80000000u;
        K = ((unsigned long long)u << 32) | (unsigned int)i;
    }

    // 8 independent branchless lower-bound searches (ILP hides LDS latency)
    int pos[8];
    #pragma unroll
    for (int c = 0; c < 8; c++) pos[c] = 0;
    #pragma unroll
    for (int st = 128; st >= 1; st >>= 1) {
        #pragma unroll
        for (int c = 0; c < 8; c++)
            if (skey[(c << 8) + pos[c] + st - 1] < K) pos[c] += st;
    }
    #pragma unroll
    for (int c = 0; c < 8; c++)
        if (skey[(c << 8) + pos[c]] < K) pos[c]++;   // pos in [0,256]

    int r = 0;
    float P = 0.f, T = 0.f;
    #pragma unroll
    for (int c = 0; c < 8; c++) {
        r += pos[c];
        if (pos[c] > 0) P += spref[(c << 8) + pos[c] - 1];
        T += spref[(c << 8) + 255];
    }

    const float B = fmaf(s, (float)(2 * r - DIM), T - 2.f * P);
    g_bsum[(b << 11) + i] = B * LOG2E;
    if (r >= DIM - KTOP) {                     // ranks 1792..2047 -> 256 slots
        g_topv[(b << 8) + (r - (DIM - KTOP))] = s * LOG2E;
        g_topB[(b << 8) + (r - (DIM - KTOP))] = B * LOG2E;
    }
}

// ---------------------------------------------------------------------------
// Kernel C: fused softmax writer. M_k is ANALYTIC (rank 2047-k element), so
// per k there is only the sum reduction (1 barrier, double-buffered slots).
// Grid (32 kg, 32 b) x 256 threads, 8 elems/thread resident, EX2 once.
// ---------------------------------------------------------------------------
__global__ __launch_bounds__(256) void softmax_kernel(const float* __restrict__ scores,
                                                      float* __restrict__ out) {
    __shared__ float redS[16];                 // double-buffered 8-warp sums
    const int kg = blockIdx.x, b = blockIdx.y, t = threadIdx.x;
    const int lane = t & 31, w = t >> 5;

    const float4* sc4 = (const float4*)(scores + (b << 11));
    const float4* bs4 = (const float4*)(g_bsum + (b << 11));
    float4 a0 = sc4[t], a1 = sc4[t + 256];
    const float4 c0 = bs4[t], c1 = bs4[t + 256];
    a0.x *= LOG2E; a0.y *= LOG2E; a0.z *= LOG2E; a0.w *= LOG2E;
    a1.x *= LOG2E; a1.y *= LOG2E; a1.z *= LOG2E; a1.w *= LOG2E;

    // prefetch the 8 (topv, topB) pairs: slot = 255-k, k = kg*8+kk
    float tv[8], tB[8];
    {
        const float4* v4 = (const float4*)(g_topv + (b << 8) + ((31 - kg) << 3));
        const float4* B4 = (const float4*)(g_topB + (b << 8) + ((31 - kg) << 3));
        float4 q0 = v4[0], q1 = v4[1], p0 = B4[0], p1 = B4[1];
        tv[0] = q0.x; tv[1] = q0.y; tv[2] = q0.z; tv[3] = q0.w;
        tv[4] = q1.x; tv[5] = q1.y; tv[6] = q1.z; tv[7] = q1.w;
        tB[0] = p0.x; tB[1] = p0.y; tB[2] = p0.z; tB[3] = p0.w;
        tB[4] = p1.x; tB[5] = p1.y; tB[6] = p1.z; tB[7] = p1.w;
    }

    #pragma unroll
    for (int kk = 0; kk < 8; kk++) {
        const int k = (kg << 3) + kk;
        const float scal = (float)(DIM - 1 - 2 * k);
        const float M = fmaf(scal, tv[7 - kk], -tB[7 - kk]);  // base-2 max

        float e[8];
        e[0] = ex2f(fmaf(a0.x, scal, -c0.x) - M);
        e[1] = ex2f(fmaf(a0.y, scal, -c0.y) - M);
        e[2] = ex2f(fmaf(a0.z, scal, -c0.z) - M);
        e[3] = ex2f(fmaf(a0.w, scal, -c0.w) - M);
        e[4] = ex2f(fmaf(a1.x, scal, -c1.x) - M);
        e[5] = ex2f(fmaf(a1.y, scal, -c1.y) - M);
        e[6] = ex2f(fmaf(a1.z, scal, -c1.z) - M);
        e[7] = ex2f(fmaf(a1.w, scal, -c1.w) - M);

        float s = ((e[0] + e[1]) + (e[2] + e[3])) + ((e[4] + e[5]) + (e[6] + e[7]));
        #pragma unroll
        for (int o = 16; o; o >>= 1) s += __shfl_xor_sync(0xffffffffu, s, o);
        const int p = (kk & 1) << 3;
        if (lane == 0) redS[p + w] = s;
        __syncthreads();
        float S = redS[p + (lane & 7)];
        #pragma unroll
        for (int o = 4; o; o >>= 1) S += __shfl_xor_sync(0xffffffffu, S, o);

        const float inv = rcpf(S);
        float4* out4 = (float4*)(out + ((size_t)((b << 8) + k) << 11));
        out4[t]       = make_float4(e[0] * inv, e[1] * inv, e[2] * inv, e[3] * inv);
        out4[t + 256] = make_float4(e[4] * inv, e[5] * inv, e[6] * inv, e[7] * inv);
    }
}

extern "C" void kernel_launch(void* const* d_in, const int* in_sizes, int n_in,
                              void* d_out, int out_size) {
    const float* scores = (const float*)d_in[0];
    float* out = (float*)d_out;

    chunk_sort_kernel<<<dim3(DIM / 256, BATCH), 256>>>(scores);
    bsum_search_kernel<<<dim3(DIM / 256, BATCH), 256>>>(scores);
    softmax_kernel<<<dim3(KTOP / 8, BATCH), 256>>>(scores, out);
}

// round 9
// speedup vs baseline: 1.7813x; 1.1362x over previous
#include <cuda_runtime.h>
#include <cuda_bf16.h>

#define DIM    2048
#define BATCH  32
#define KTOP   256
#define LOG2E  1.44269504f

// sorted chunk keys [b][chunk][256]: (monotonic u32 key << 32) | global index
__device__ __align__(16) unsigned long long g_key[BATCH * DIM];
// inclusive prefix sums of values in chunk-sorted order, same layout
__device__ __align__(16) float g_pref[BATCH * DIM];
// Bsum * log2e, original index order
__device__ __align__(16) float g_bsum[BATCH * DIM];
// top-256 by global rank: slot r-1792 holds (s*log2e, B*log2e) of rank-r element
__device__ __align__(16) float g_topv[BATCH * KTOP];
__device__ __align__(16) float g_topB[BATCH * KTOP];

__device__ __forceinline__ float ex2f(float x) {
    float r; asm("ex2.approx.ftz.f32 %0, %1;" : "=f"(r) : "f"(x)); return r;
}
__device__ __forceinline__ float rcpf(float x) {
    float r; asm("rcp.approx.f32 %0, %1;" : "=f"(r) : "f"(x)); return r;
}
__device__ __forceinline__ unsigned long long cmpex_shfl(unsigned long long v,
                                                         int t, int j, bool d) {
    unsigned long long o = __shfl_xor_sync(0xffffffffu, v, j);
    bool takeMin = (((t & j) == 0) == d);
    return (takeMin ? (o < v) : (o > v)) ? o : v;
}

// ---------------------------------------------------------------------------
// Kernel A: sort one 256-element chunk of TWO batch rows per block (ILP-2 on
// the bitonic compare-exchange chain). Grid (8 chunks, 16 row-pairs) x 256.
// Outputs sorted (key,idx) u64 and inclusive value-prefix sums per chunk.
// ---------------------------------------------------------------------------
__global__ __launch_bounds__(256) void chunk_sort_kernel(const float* __restrict__ scores) {
    __shared__ unsigned long long buf0[256], buf1[256];
    __shared__ float wtot[2][8];
    const int chunk = blockIdx.x, bp = blockIdx.y, t = threadIdx.x;
    const int lane = t & 31, w = t >> 5;
    const int b0 = bp * 2, b1 = b0 + 1;
    const int gi = (chunk << 8) + t;

    unsigned long long K0, K1;
    {
        unsigned int u = __float_as_uint(scores[(b0 << 11) + gi]);
        u ^= ((unsigned int)((int)u >> 31)) | 0x80000000u;
        K0 = ((unsigned long long)u << 32) | (unsigned int)gi;
        u = __float_as_uint(scores[(b1 << 11) + gi]);
        u ^= ((unsigned int)((int)u >> 31)) | 0x80000000u;
        K1 = ((unsigned long long)u << 32) | (unsigned int)gi;
    }

    // stages k=2..32: intra-warp shfl, two independent networks interleaved
    #pragma unroll
    for (int k = 2; k <= 32; k <<= 1) {
        const bool d = ((t & k) == 0);
        #pragma unroll
        for (int j = k >> 1; j > 0; j >>= 1) {
            K0 = cmpex_shfl(K0, t, j, d);
            K1 = cmpex_shfl(K1, t, j, d);
        }
    }
    // stages k=64..256: j>=32 via smem, rest shfl
    #pragma unroll
    for (int k = 64; k <= 256; k <<= 1) {
        const bool d = ((t & k) == 0);
        #pragma unroll
        for (int j = k >> 1; j > 0; j >>= 1) {
            if (j >= 32) {
                __syncthreads();
                buf0[t] = K0; buf1[t] = K1;
                __syncthreads();
                unsigned long long o0 = buf0[t ^ j];
                unsigned long long o1 = buf1[t ^ j];
                bool takeMin = (((t & j) == 0) == d);
                K0 = (takeMin ? (o0 < K0) : (o0 > K0)) ? o0 : K0;
                K1 = (takeMin ? (o1 < K1) : (o1 > K1)) ? o1 : K1;
            } else {
                K0 = cmpex_shfl(K0, t, j, d);
                K1 = cmpex_shfl(K1, t, j, d);
            }
        }
    }

    // decode values at sorted position t
    float v0, v1;
    {
        unsigned int u = (unsigned int)(K0 >> 32);
        u ^= (~((unsigned int)((int)u >> 31))) | 0x80000000u;
        v0 = __uint_as_float(u);
        u = (unsigned int)(K1 >> 32);
        u ^= (~((unsigned int)((int)u >> 31))) | 0x80000000u;
        v1 = __uint_as_float(u);
    }

    // two interleaved inclusive block scans
    float x0 = v0, x1 = v1;
    #pragma unroll
    for (int o = 1; o < 32; o <<= 1) {
        float y0 = __shfl_up_sync(0xffffffffu, x0, o);
        float y1 = __shfl_up_sync(0xffffffffu, x1, o);
        if (lane >= o) { x0 += y0; x1 += y1; }
    }
    if (lane == 31) { wtot[0][w] = x0; wtot[1][w] = x1; }
    __syncthreads();
    float off0 = 0.f, off1 = 0.f;
    #pragma unroll
    for (int ww = 0; ww < 7; ww++)
        if (ww < w) { off0 += wtot[0][ww]; off1 += wtot[1][ww]; }

    g_key[(b0 << 11) + gi]  = K0;
    g_key[(b1 << 11) + gi]  = K1;
    g_pref[(b0 << 11) + gi] = off0 + x0;
    g_pref[(b1 << 11) + gi] = off1 + x1;
}

// ---------------------------------------------------------------------------
// Kernel B: Bsum via 8 interleaved branchless binary searches over the sorted
// chunks (staged in smem) + top-256 scatter by global rank. The query key is
// the staged key itself (own-chunk search returns its own position).
// B_i = s_i*(2r-n) + T - 2P ; rank 2047-k element is the softmax argmax.
// ---------------------------------------------------------------------------
__global__ __launch_bounds__(256) void bsum_search_kernel() {
    __shared__ __align__(16) unsigned long long skey[DIM];  // 16 KB
    __shared__ __align__(16) float spref[DIM];              // 8 KB
    const int ic = blockIdx.x, b = blockIdx.y, t = threadIdx.x;

    {   // stage the whole row's sorted chunks
        const ulonglong2* gk2 = (const ulonglong2*)(g_key + (b << 11));
        ulonglong2* sk2 = (ulonglong2*)skey;
        #pragma unroll
        for (int c = 0; c < 4; c++) sk2[t + c * 256] = gk2[t + c * 256];
        const float4* gp4 = (const float4*)(g_pref + (b << 11));
        float4* sp4 = (float4*)spref;
        #pragma unroll
        for (int c = 0; c < 2; c++) sp4[t + c * 256] = gp4[t + c * 256];
    }
    __syncthreads();

    // this thread's element: sorted slot t of chunk ic
    const unsigned long long K = skey[(ic << 8) + t];
    const unsigned int idx = (unsigned int)(K & 0xFFFFFFFFu);
    float s;
    {
        unsigned int u = (unsigned int)(K >> 32);
        u ^= (~((unsigned int)((int)u >> 31))) | 0x80000000u;
        s = __uint_as_float(u);
    }

    // 8 independent branchless lower-bound searches (ILP hides LDS latency)
    int pos[8];
    #pragma unroll
    for (int c = 0; c < 8; c++) pos[c] = 0;
    #pragma unroll
    for (int st = 128; st >= 1; st >>= 1) {
        #pragma unroll
        for (int c = 0; c < 8; c++)
            if (skey[(c << 8) + pos[c] + st - 1] < K) pos[c] += st;
    }
    #pragma unroll
    for (int c = 0; c < 8; c++)
        if (skey[(c << 8) + pos[c]] < K) pos[c]++;   // pos in [0,256]

    int r = 0;
    float P = 0.f, T = 0.f;
    #pragma unroll
    for (int c = 0; c < 8; c++) {
        r += pos[c];
        if (pos[c] > 0) P += spref[(c << 8) + pos[c] - 1];
        T += spref[(c << 8) + 255];
    }

    const float B = fmaf(s, (float)(2 * r - DIM), T - 2.f * P);
    g_bsum[(b << 11) + idx] = B * LOG2E;
    if (r >= DIM - KTOP) {                     // ranks 1792..2047 -> 256 slots
        g_topv[(b << 8) + (r - (DIM - KTOP))] = s * LOG2E;
        g_topB[(b << 8) + (r - (DIM - KTOP))] = B * LOG2E;
    }
}

// ---------------------------------------------------------------------------
// Kernel C: fused softmax writer, k's processed in PAIRS. M is analytic
// (rank 2047-k element => slot 255-k), so per pair there is one barrier and
// two overlapping independent shuffle chains. Double-buffered reduction
// slots eliminate the trailing barrier. Grid (32 kg, 32 b) x 256 threads.
// ---------------------------------------------------------------------------
__global__ __launch_bounds__(256) void softmax_kernel(const float* __restrict__ scores,
                                                      float* __restrict__ out) {
    __shared__ float redS[32];                 // 2 buffers x (8+8) warp sums
    const int kg = blockIdx.x, b = blockIdx.y, t = threadIdx.x;
    const int lane = t & 31, w = t >> 5;

    const float4* sc4 = (const float4*)(scores + (b << 11));
    const float4* bs4 = (const float4*)(g_bsum + (b << 11));
    float4 a0 = sc4[t], a1 = sc4[t + 256];
    const float4 c0 = bs4[t], c1 = bs4[t + 256];
    a0.x *= LOG2E; a0.y *= LOG2E; a0.z *= LOG2E; a0.w *= LOG2E;
    a1.x *= LOG2E; a1.y *= LOG2E; a1.z *= LOG2E; a1.w *= LOG2E;

    #pragma unroll
    for (int kp = 0; kp < 4; kp++) {
        const int k0 = (kg << 3) + 2 * kp;
        const int k1 = k0 + 1;
        const float scal0 = (float)(DIM - 1 - 2 * k0);
        const float scal1 = (float)(DIM - 1 - 2 * k1);
        // analytic base-2 maxima from rank 2047-k elements (slot 255-k)
        const float M0 = fmaf(scal0, __ldg(&g_topv[(b << 8) + 255 - k0]),
                              -__ldg(&g_topB[(b << 8) + 255 - k0]));
        const float M1 = fmaf(scal1, __ldg(&g_topv[(b << 8) + 255 - k1]),
                              -__ldg(&g_topB[(b << 8) + 255 - k1]));

        float e0[8], e1[8];
        e0[0] = ex2f(fmaf(a0.x, scal0, -c0.x) - M0);
        e0[1] = ex2f(fmaf(a0.y, scal0, -c0.y) - M0);
        e0[2] = ex2f(fmaf(a0.z, scal0, -c0.z) - M0);
        e0[3] = ex2f(fmaf(a0.w, scal0, -c0.w) - M0);
        e0[4] = ex2f(fmaf(a1.x, scal0, -c1.x) - M0);
        e0[5] = ex2f(fmaf(a1.y, scal0, -c1.y) - M0);
        e0[6] = ex2f(fmaf(a1.z, scal0, -c1.z) - M0);
        e0[7] = ex2f(fmaf(a1.w, scal0, -c1.w) - M0);
        e1[0] = ex2f(fmaf(a0.x, scal1, -c0.x) - M1);
        e1[1] = ex2f(fmaf(a0.y, scal1, -c0.y) - M1);
        e1[2] = ex2f(fmaf(a0.z, scal1, -c0.z) - M1);
        e1[3] = ex2f(fmaf(a0.w, scal1, -c0.w) - M1);
        e1[4] = ex2f(fmaf(a1.x, scal1, -c1.x) - M1);
        e1[5] = ex2f(fmaf(a1.y, scal1, -c1.y) - M1);
        e1[6] = ex2f(fmaf(a1.z, scal1, -c1.z) - M1);
        e1[7] = ex2f(fmaf(a1.w, scal1, -c1.w) - M1);

        float s0 = ((e0[0] + e0[1]) + (e0[2] + e0[3])) + ((e0[4] + e0[5]) + (e0[6] + e0[7]));
        float s1 = ((e1[0] + e1[1]) + (e1[2] + e1[3])) + ((e1[4] + e1[5]) + (e1[6] + e1[7]));
        #pragma unroll
        for (int o = 16; o; o >>= 1) {       // two independent chains overlap
            s0 += __shfl_xor_sync(0xffffffffu, s0, o);
            s1 += __shfl_xor_sync(0xffffffffu, s1, o);
        }
        const int p = (kp & 1) << 4;
        if (lane == 0) { redS[p + w] = s0; redS[p + 8 + w] = s1; }
        __syncthreads();                     // one barrier per 2 k's
        float S0 = redS[p + (lane & 7)];
        float S1 = redS[p + 8 + (lane & 7)];
        #pragma unroll
        for (int o = 4; o; o >>= 1) {
            S0 += __shfl_xor_sync(0xffffffffu, S0, o);
            S1 += __shfl_xor_sync(0xffffffffu, S1, o);
        }

        const float i0 = rcpf(S0);
        const float i1 = rcpf(S1);
        float4* o0p = (float4*)(out + ((size_t)((b << 8) + k0) << 11));
        float4* o1p = (float4*)(out + ((size_t)((b << 8) + k1) << 11));
        o0p[t]       = make_float4(e0[0] * i0, e0[1] * i0, e0[2] * i0, e0[3] * i0);
        o0p[t + 256] = make_float4(e0[4] * i0, e0[5] * i0, e0[6] * i0, e0[7] * i0);
        o1p[t]       = make_float4(e1[0] * i1, e1[1] * i1, e1[2] * i1, e1[3] * i1);
        o1p[t + 256] = make_float4(e1[4] * i1, e1[5] * i1, e1[6] * i1, e1[7] * i1);
    }
}

extern "C" void kernel_launch(void* const* d_in, const int* in_sizes, int n_in,
                              void* d_out, int out_size) {
    const float* scores = (const float*)d_in[0];
    float* out = (float*)d_out;

    chunk_sort_kernel<<<dim3(DIM / 256, BATCH / 2), 256>>>(scores);
    bsum_search_kernel<<<dim3(DIM / 256, BATCH), 256>>>();
    softmax_kernel<<<dim3(KTOP / 8, BATCH), 256>>>(scores, out);
}